// round 2
// baseline (speedup 1.0000x reference)
#include <cuda_runtime.h>
#include <math.h>

// Problem constants (fixed by setup_inputs)
#define D        128
#define GMAXX    256
#define NMAXX    50048
#define BN_EPS   1e-5f

// ---------------- scratch (device globals; no allocation allowed) ----------------
__device__ float g_hA[NMAXX * D];
__device__ float g_hB[NMAXX * D];
__device__ float g_z[NMAXX * D];
__device__ float g_agg[NMAXX * D];
__device__ float g_el[NMAXX * 8];
__device__ float g_er[NMAXX * 8];
__device__ float g_emax[NMAXX * 8];
__device__ float g_denom[NMAXX * 8];
__device__ float g_wflat[D * D];
__device__ float g_bnsum[D];
__device__ float g_bnsq[D];
__device__ float g_gsum[GMAXX * D];
__device__ int   g_gcnt[GMAXX];

// ---------------- init ----------------
__global__ void k_init(int N, int H) {
    int i = blockIdx.x * blockDim.x + threadIdx.x;
    if (i < N * D) g_agg[i] = 0.f;
    if (i < N * H) { g_denom[i] = 0.f; g_emax[i] = -INFINITY; }
    if (i < D) { g_bnsum[i] = 0.f; g_bnsq[i] = 0.f; }
}

__global__ void k_zero_readout() {
    int i = blockIdx.x * blockDim.x + threadIdx.x;
    if (i < GMAXX * D) g_gsum[i] = 0.f;
    if (i < GMAXX) g_gcnt[i] = 0;
}

// ---------------- GEMM: C[N,128] = A[N,128] * B[128,128] (+ bias) ----------------
// 64x64 tile per block (grid.x = 2 col tiles), 256 threads, 4x4 microtile.
__global__ void k_gemm(const float* __restrict__ A, const float* __restrict__ B,
                       const float* __restrict__ bias, float* __restrict__ C, int N)
{
    __shared__ __align__(16) float Ast[16][68]; // [k][row], padded
    __shared__ __align__(16) float Bs[16][64];  // [k][col]
    int tid = threadIdx.x;
    int tx = tid & 15, ty = tid >> 4;
    int row0 = blockIdx.y * 64;
    int col0 = blockIdx.x * 64;

    float acc[4][4];
#pragma unroll
    for (int i = 0; i < 4; i++)
#pragma unroll
        for (int j = 0; j < 4; j++) acc[i][j] = 0.f;

    for (int kt = 0; kt < 8; kt++) {
        // A tile: 64 rows x 16 k, transposed into Ast[k][row]
        {
            int r = tid >> 2;            // 0..63
            int kq = (tid & 3) * 4;      // 0,4,8,12
            int gr = row0 + r; if (gr >= N) gr = N - 1;
            const float4 av = *(const float4*)(A + (size_t)gr * D + kt * 16 + kq);
            Ast[kq + 0][r] = av.x; Ast[kq + 1][r] = av.y;
            Ast[kq + 2][r] = av.z; Ast[kq + 3][r] = av.w;
        }
        // B tile: 16 k x 64 cols
        {
            int k = tid >> 4;            // 0..15
            int c4 = (tid & 15) * 4;
            *(float4*)&Bs[k][c4] = *(const float4*)(B + (size_t)(kt * 16 + k) * D + col0 + c4);
        }
        __syncthreads();
#pragma unroll
        for (int k = 0; k < 16; k++) {
            float4 a = *(float4*)&Ast[k][ty * 4];
            float4 b = *(float4*)&Bs[k][tx * 4];
            acc[0][0] += a.x * b.x; acc[0][1] += a.x * b.y; acc[0][2] += a.x * b.z; acc[0][3] += a.x * b.w;
            acc[1][0] += a.y * b.x; acc[1][1] += a.y * b.y; acc[1][2] += a.y * b.z; acc[1][3] += a.y * b.w;
            acc[2][0] += a.z * b.x; acc[2][1] += a.z * b.y; acc[2][2] += a.z * b.z; acc[2][3] += a.z * b.w;
            acc[3][0] += a.w * b.x; acc[3][1] += a.w * b.y; acc[3][2] += a.w * b.z; acc[3][3] += a.w * b.w;
        }
        __syncthreads();
    }

    int c0 = col0 + tx * 4;
    float4 bv = make_float4(0.f, 0.f, 0.f, 0.f);
    if (bias) bv = *(const float4*)(bias + c0);
#pragma unroll
    for (int i = 0; i < 4; i++) {
        int r = row0 + ty * 4 + i;
        if (r < N) {
            float4 v = make_float4(acc[i][0] + bv.x, acc[i][1] + bv.y,
                                   acc[i][2] + bv.z, acc[i][3] + bv.w);
            *(float4*)(C + (size_t)r * D + c0) = v;
        }
    }
}

// ---------------- weight reshape: wflat[d*128 + h*16+o] = fcW[h][d][o] ----------------
__global__ void k_transpose(const float* __restrict__ fcWl) {
    int i = blockIdx.x * blockDim.x + threadIdx.x;
    if (i >= D * D) return;
    int d = i >> 7, c = i & 127;
    int h = c >> 4, o = c & 15;
    g_wflat[i] = fcWl[(h * D + d) * 16 + o];
}

// ---------------- attention logits el/er ----------------
__global__ void k_attn8(const float* __restrict__ aSl, const float* __restrict__ aDl, int N) {
    int t = blockIdx.x * blockDim.x + threadIdx.x;
    if (t >= N * 8) return;
    int n = t >> 3, h = t & 7;
    const float4* zr = (const float4*)(g_z + (size_t)n * D + h * 16);
    const float4* as4 = (const float4*)(aSl + h * 16);
    const float4* ad4 = (const float4*)(aDl + h * 16);
    float s = 0.f, dd = 0.f;
#pragma unroll
    for (int q = 0; q < 4; q++) {
        float4 z = zr[q], a = as4[q], b = ad4[q];
        s += z.x * a.x + z.y * a.y + z.z * a.z + z.w * a.w;
        dd += z.x * b.x + z.y * b.y + z.z * b.z + z.w * b.w;
    }
    g_el[t] = s; g_er[t] = dd;
}

__global__ void k_attn1(const float* __restrict__ aSl, const float* __restrict__ aDl, int N) {
    int w = (blockIdx.x * blockDim.x + threadIdx.x) >> 5;
    int lane = threadIdx.x & 31;
    if (w >= N) return;
    float4 z = ((const float4*)(g_z + (size_t)w * D))[lane];
    float4 a = ((const float4*)aSl)[lane];
    float4 b = ((const float4*)aDl)[lane];
    float s = z.x * a.x + z.y * a.y + z.z * a.z + z.w * a.w;
    float dd = z.x * b.x + z.y * b.y + z.z * b.z + z.w * b.w;
#pragma unroll
    for (int o = 16; o; o >>= 1) {
        s += __shfl_xor_sync(0xffffffffu, s, o);
        dd += __shfl_xor_sync(0xffffffffu, dd, o);
    }
    if (lane == 0) { g_el[w] = s; g_er[w] = dd; }
}

// ---------------- edge pass 1: segment max (float atomicMax via sign-split) ----------------
template<int H>
__global__ void k_edge1(const int* __restrict__ src, const int* __restrict__ dst, int E) {
    int t = blockIdx.x * blockDim.x + threadIdx.x;
    if (t >= E * H) return;
    int e, h;
    if (H == 8) { e = t >> 3; h = t & 7; } else { e = t; h = 0; }
    int s = src[e], d = dst[e];
    float v = g_el[s * H + h] + g_er[d * H + h];
    v = v > 0.f ? v : 0.01f * v;
    float* addr = &g_emax[d * H + h];
    if (v >= 0.f) atomicMax((int*)addr, __float_as_int(v));
    else          atomicMin((unsigned int*)addr, __float_as_uint(v));
}

// ---------------- edge pass 2: ee, denom, weighted aggregation (warp per edge) ----------------
template<int H>
__global__ void k_edge2(const int* __restrict__ src, const int* __restrict__ dst, int E) {
    int gw = (blockIdx.x * blockDim.x + threadIdx.x) >> 5;
    int lane = threadIdx.x & 31;
    if (gw >= E) return;
    int s = src[gw], d = dst[gw];
    float ee = 0.f;
    if (lane < H) {
        float v = g_el[s * H + lane] + g_er[d * H + lane];
        v = v > 0.f ? v : 0.01f * v;
        ee = __expf(v - g_emax[d * H + lane]);
        atomicAdd(&g_denom[d * H + lane], ee);
    }
    float eh = __shfl_sync(0xffffffffu, ee, (H == 8) ? (lane >> 2) : 0);
    float4 z = ((const float4*)(g_z + (size_t)s * D))[lane];
    float* ap = g_agg + (size_t)d * D + lane * 4;
    asm volatile("red.global.add.v4.f32 [%0], {%1,%2,%3,%4};"
                 :: "l"(ap), "f"(z.x * eh), "f"(z.y * eh), "f"(z.z * eh), "f"(z.w * eh)
                 : "memory");
}

// ---------------- BN stats: t = (agg/denom)*snorm (in place), per-channel sum/sumsq ----------------
template<int H>
__global__ void k_bnstats(const float* __restrict__ snorm, int N) {
    int c = threadIdx.x & 127;
    int half = threadIdx.x >> 7;
    int h = (H == 8) ? (c >> 4) : 0;
    float sum = 0.f, sq = 0.f;
    for (int n = blockIdx.x * 2 + half; n < N; n += gridDim.x * 2) {
        float dn = g_denom[n * H + h];
        float t = (dn > 0.f) ? (g_agg[(size_t)n * D + c] / dn) : 0.f;
        t *= snorm[n];
        g_agg[(size_t)n * D + c] = t;
        sum += t; sq += t * t;
    }
    __shared__ float sS[128], sQ[128];
    if (half) { sS[c] = sum; sQ[c] = sq; }
    __syncthreads();
    if (!half) {
        atomicAdd(&g_bnsum[c], sum + sS[c]);
        atomicAdd(&g_bnsq[c], sq + sQ[c]);
    }
}

// ---------------- BN apply + ELU + residual ----------------
__global__ void k_apply(const float* __restrict__ hin, float* __restrict__ hout,
                        const float* __restrict__ gam, const float* __restrict__ bet, int N) {
    int i = blockIdx.x * blockDim.x + threadIdx.x;
    if (i >= N * D) return;
    int c = i & 127;
    float invN = 1.f / (float)N;
    float mu = g_bnsum[c] * invN;
    float var = g_bnsq[c] * invN - mu * mu;
    float x = (g_agg[i] - mu) * rsqrtf(var + BN_EPS) * gam[c] + bet[c];
    float y = x > 0.f ? x : expm1f(x);
    hout[i] = hin[i] + y;
}

// ---------------- readout: run-length segment sum (graph_ids sorted) ----------------
__global__ void k_readout(const float* __restrict__ h, const int* __restrict__ gid, int N) {
    int c = threadIdx.x; // 128
    int chunk = (N + gridDim.x - 1) / gridDim.x;
    int n0 = blockIdx.x * chunk;
    int n1 = n0 + chunk; if (n1 > N) n1 = N;
    float acc = 0.f; int gcur = -1, cnt = 0;
    for (int n = n0; n < n1; n++) {
        int g = gid[n];
        if (g != gcur) {
            if (gcur >= 0) {
                atomicAdd(&g_gsum[gcur * D + c], acc);
                if (c == 0) atomicAdd(&g_gcnt[gcur], cnt);
            }
            acc = 0.f; cnt = 0; gcur = g;
        }
        acc += h[(size_t)n * D + c]; cnt++;
    }
    if (gcur >= 0) {
        atomicAdd(&g_gsum[gcur * D + c], acc);
        if (c == 0) atomicAdd(&g_gcnt[gcur], cnt);
    }
}

// ---------------- MLP readout: 128 -> 64 -> 32 -> 10 per graph ----------------
__global__ void k_mlp(const float* __restrict__ w1, const float* __restrict__ b1,
                      const float* __restrict__ w2, const float* __restrict__ b2,
                      const float* __restrict__ w3, const float* __restrict__ b3,
                      float* __restrict__ out) {
    int g = blockIdx.x, t = threadIdx.x; // 128 threads
    __shared__ float sh[128], s1[64], s2[32];
    float cnt = (float)g_gcnt[g]; if (cnt < 1.f) cnt = 1.f;
    sh[t] = g_gsum[g * D + t] / cnt;
    __syncthreads();
    if (t < 64) {
        float a = b1[t];
        for (int k = 0; k < 128; k++) a += sh[k] * w1[k * 64 + t];
        s1[t] = a > 0.f ? a : 0.f;
    }
    __syncthreads();
    if (t < 32) {
        float a = b2[t];
        for (int k = 0; k < 64; k++) a += s1[k] * w2[k * 32 + t];
        s2[t] = a > 0.f ? a : 0.f;
    }
    __syncthreads();
    if (t < 10) {
        float a = b3[t];
        for (int k = 0; k < 32; k++) a += s2[k] * w3[k * 10 + t];
        out[g * 10 + t] = a;
    }
}

// ---------------- host orchestration ----------------
static float* symf(const void* s) { void* p = nullptr; cudaGetSymbolAddress(&p, s); return (float*)p; }

extern "C" void kernel_launch(void* const* d_in, const int* in_sizes, int n_in,
                              void* d_out, int out_size) {
    const float* nodes_feat = (const float*)d_in[0];
    const float* snorm      = (const float*)d_in[1];
    const float* emb_W      = (const float*)d_in[2];
    const float* emb_b      = (const float*)d_in[3];
    const float* fcW        = (const float*)d_in[4];
    const float* aS         = (const float*)d_in[5];
    const float* aD         = (const float*)d_in[6];
    const float* gamma      = (const float*)d_in[7];
    const float* beta       = (const float*)d_in[8];
    const float* fcW_last   = (const float*)d_in[9];
    const float* aS_last    = (const float*)d_in[10];
    const float* aD_last    = (const float*)d_in[11];
    const float* g_last     = (const float*)d_in[12];
    const float* b_last     = (const float*)d_in[13];
    const float* w1 = (const float*)d_in[14]; const float* b1 = (const float*)d_in[15];
    const float* w2 = (const float*)d_in[16]; const float* b2 = (const float*)d_in[17];
    const float* w3 = (const float*)d_in[18]; const float* b3 = (const float*)d_in[19];
    const int* src = (const int*)d_in[20];
    const int* dst = (const int*)d_in[21];
    const int* gid = (const int*)d_in[22];

    int N = in_sizes[0] / D;
    int E = in_sizes[20];
    float* out = (float*)d_out;

    float* hA = symf(g_hA);
    float* hB = symf(g_hB);
    float* zp = symf(g_z);
    float* wf = symf(g_wflat);

    dim3 ggrid(2, (N + 63) / 64);
    int nd_blocks = (N * D + 255) / 256;

    // embedding
    k_gemm<<<ggrid, 256>>>(nodes_feat, emb_W, emb_b, hA, N);

    const float* hin = hA;
    float* hout = hB;

    // 3 multi-head layers (H=8, O=16)
    for (int l = 0; l < 3; l++) {
        k_transpose<<<(D * D + 255) / 256, 256>>>(fcW + (size_t)l * 8 * D * 16);
        k_gemm<<<ggrid, 256>>>(hin, wf, nullptr, zp, N);
        k_attn8<<<(N * 8 + 255) / 256, 256>>>(aS + l * 128, aD + l * 128, N);
        k_init<<<nd_blocks, 256>>>(N, 8);
        k_edge1<8><<<(E * 8 + 255) / 256, 256>>>(src, dst, E);
        k_edge2<8><<<(E * 32 + 255) / 256, 256>>>(src, dst, E);
        k_bnstats<8><<<256, 256>>>(snorm, N);
        k_apply<<<nd_blocks, 256>>>(hin, hout, gamma + l * 128, beta + l * 128, N);
        const float* tmp = hin; hin = hout; hout = (float*)tmp;
    }

    // last layer (H=1, O=128): fcW_last is already [d][o] row-major
    {
        k_gemm<<<ggrid, 256>>>(hin, fcW_last, nullptr, zp, N);
        k_attn1<<<(N * 32 + 255) / 256, 256>>>(aS_last, aD_last, N);
        k_init<<<nd_blocks, 256>>>(N, 1);
        k_edge1<1><<<(E + 255) / 256, 256>>>(src, dst, E);
        k_edge2<1><<<(E * 32 + 255) / 256, 256>>>(src, dst, E);
        k_bnstats<1><<<256, 256>>>(snorm, N);
        k_apply<<<nd_blocks, 256>>>(hin, hout, g_last, b_last, N);
        const float* tmp = hin; hin = hout; hout = (float*)tmp;
    }

    // readout
    k_zero_readout<<<(GMAXX * D + 255) / 256, 256>>>();
    k_readout<<<512, 128>>>(hin, gid, N);
    k_mlp<<<GMAXX, 128>>>(w1, b1, w2, b2, w3, b3, out);
}

// round 4
// speedup vs baseline: 1.9996x; 1.9996x over previous
#include <cuda_runtime.h>
#include <math.h>

// Problem constants (fixed by setup_inputs)
#define D        128
#define GMAXX    256
#define NMAXX    50048
#define EMAXX    1600000
#define BN_EPS   1e-5f

// ---------------- scratch (device globals; no allocation allowed) ----------------
__device__ float g_hA[NMAXX * D];
__device__ float g_hB[NMAXX * D];
__device__ float g_z[NMAXX * D];
__device__ float g_agg[NMAXX * D];
__device__ float g_el[NMAXX * 8];
__device__ float g_er[NMAXX * 8];
__device__ float g_wflat[D * D];
__device__ float g_bnsum[D];
__device__ float g_bnsq[D];
__device__ float g_gsum[GMAXX * D];
__device__ int   g_gcnt[GMAXX];
// CSR scratch
__device__ int   g_cnt[NMAXX];
__device__ int   g_rowptr[NMAXX + 1];
__device__ int   g_cursor[NMAXX];
__device__ int   g_srcs[EMAXX];

// ---------------- CSR build ----------------
__global__ void k_zero_cnt(int N) {
    int i = blockIdx.x * blockDim.x + threadIdx.x;
    if (i < N) g_cnt[i] = 0;
}

__global__ void k_hist(const int* __restrict__ dst, int E) {
    int e = blockIdx.x * blockDim.x + threadIdx.x;
    if (e < E) atomicAdd(&g_cnt[dst[e]], 1);
}

// single-block exclusive scan over g_cnt -> g_rowptr/g_cursor (warp-shuffle based)
__global__ void k_scan(int N, int E) {
    __shared__ int warp_sums[32];
    __shared__ int s_carry;
    int t = threadIdx.x;          // 1024 threads
    int lane = t & 31, wid = t >> 5;
    if (t == 0) s_carry = 0;
    __syncthreads();
    for (int base = 0; base < N; base += 1024) {
        int i = base + t;
        int v = (i < N) ? g_cnt[i] : 0;
        // warp inclusive scan
        int x = v;
#pragma unroll
        for (int off = 1; off < 32; off <<= 1) {
            int y = __shfl_up_sync(0xffffffffu, x, off);
            if (lane >= off) x += y;
        }
        if (lane == 31) warp_sums[wid] = x;
        __syncthreads();
        if (wid == 0) {
            int w = warp_sums[lane];
#pragma unroll
            for (int off = 1; off < 32; off <<= 1) {
                int y = __shfl_up_sync(0xffffffffu, w, off);
                if (lane >= off) w += y;
            }
            warp_sums[lane] = w;
        }
        __syncthreads();
        int incl = x + (wid > 0 ? warp_sums[wid - 1] : 0);
        int excl = incl - v + s_carry;
        if (i < N) { g_rowptr[i] = excl; g_cursor[i] = excl; }
        __syncthreads();
        if (t == 1023) s_carry += incl;
        __syncthreads();
    }
    if (t == 0) g_rowptr[N] = E;
}

__global__ void k_scatter(const int* __restrict__ src, const int* __restrict__ dst, int E) {
    int e = blockIdx.x * blockDim.x + threadIdx.x;
    if (e >= E) return;
    int d = dst[e];
    int pos = atomicAdd(&g_cursor[d], 1);
    g_srcs[pos] = src[e];
}

// ---------------- misc init ----------------
__global__ void k_zero_bn() {
    int i = threadIdx.x;
    if (i < D) { g_bnsum[i] = 0.f; g_bnsq[i] = 0.f; }
}

__global__ void k_zero_readout() {
    int i = blockIdx.x * blockDim.x + threadIdx.x;
    if (i < GMAXX * D) g_gsum[i] = 0.f;
    if (i < GMAXX) g_gcnt[i] = 0;
}

// ---------------- GEMM: C[N,128] = A[N,128] * B[128,128] (+ bias) ----------------
__global__ void k_gemm(const float* __restrict__ A, const float* __restrict__ B,
                       const float* __restrict__ bias, float* __restrict__ C, int N)
{
    __shared__ __align__(16) float Ast[16][68]; // [k][row], padded
    __shared__ __align__(16) float Bs[16][64];  // [k][col]
    int tid = threadIdx.x;
    int tx = tid & 15, ty = tid >> 4;
    int row0 = blockIdx.y * 64;
    int col0 = blockIdx.x * 64;

    float acc[4][4];
#pragma unroll
    for (int i = 0; i < 4; i++)
#pragma unroll
        for (int j = 0; j < 4; j++) acc[i][j] = 0.f;

    for (int kt = 0; kt < 8; kt++) {
        {
            int r = tid >> 2;
            int kq = (tid & 3) * 4;
            int gr = row0 + r; if (gr >= N) gr = N - 1;
            const float4 av = *(const float4*)(A + (size_t)gr * D + kt * 16 + kq);
            Ast[kq + 0][r] = av.x; Ast[kq + 1][r] = av.y;
            Ast[kq + 2][r] = av.z; Ast[kq + 3][r] = av.w;
        }
        {
            int k = tid >> 4;
            int c4 = (tid & 15) * 4;
            *(float4*)&Bs[k][c4] = *(const float4*)(B + (size_t)(kt * 16 + k) * D + col0 + c4);
        }
        __syncthreads();
#pragma unroll
        for (int k = 0; k < 16; k++) {
            float4 a = *(float4*)&Ast[k][ty * 4];
            float4 b = *(float4*)&Bs[k][tx * 4];
            acc[0][0] += a.x * b.x; acc[0][1] += a.x * b.y; acc[0][2] += a.x * b.z; acc[0][3] += a.x * b.w;
            acc[1][0] += a.y * b.x; acc[1][1] += a.y * b.y; acc[1][2] += a.y * b.z; acc[1][3] += a.y * b.w;
            acc[2][0] += a.z * b.x; acc[2][1] += a.z * b.y; acc[2][2] += a.z * b.z; acc[2][3] += a.z * b.w;
            acc[3][0] += a.w * b.x; acc[3][1] += a.w * b.y; acc[3][2] += a.w * b.z; acc[3][3] += a.w * b.w;
        }
        __syncthreads();
    }

    int c0 = col0 + tx * 4;
    float4 bv = make_float4(0.f, 0.f, 0.f, 0.f);
    if (bias) bv = *(const float4*)(bias + c0);
#pragma unroll
    for (int i = 0; i < 4; i++) {
        int r = row0 + ty * 4 + i;
        if (r < N) {
            float4 v = make_float4(acc[i][0] + bv.x, acc[i][1] + bv.y,
                                   acc[i][2] + bv.z, acc[i][3] + bv.w);
            *(float4*)(C + (size_t)r * D + c0) = v;
        }
    }
}

// ---------------- weight reshape: wflat[d*128 + h*16+o] = fcW[h][d][o] ----------------
__global__ void k_transpose(const float* __restrict__ fcWl) {
    int i = blockIdx.x * blockDim.x + threadIdx.x;
    if (i >= D * D) return;
    int d = i >> 7, c = i & 127;
    int h = c >> 4, o = c & 15;
    g_wflat[i] = fcWl[(h * D + d) * 16 + o];
}

// ---------------- attention logits el/er ----------------
__global__ void k_attn8(const float* __restrict__ aSl, const float* __restrict__ aDl, int N) {
    int t = blockIdx.x * blockDim.x + threadIdx.x;
    if (t >= N * 8) return;
    int n = t >> 3, h = t & 7;
    const float4* zr = (const float4*)(g_z + (size_t)n * D + h * 16);
    const float4* as4 = (const float4*)(aSl + h * 16);
    const float4* ad4 = (const float4*)(aDl + h * 16);
    float s = 0.f, dd = 0.f;
#pragma unroll
    for (int q = 0; q < 4; q++) {
        float4 z = zr[q], a = as4[q], b = ad4[q];
        s += z.x * a.x + z.y * a.y + z.z * a.z + z.w * a.w;
        dd += z.x * b.x + z.y * b.y + z.z * b.z + z.w * b.w;
    }
    g_el[t] = s; g_er[t] = dd;
}

__global__ void k_attn1(const float* __restrict__ aSl, const float* __restrict__ aDl, int N) {
    int w = (blockIdx.x * blockDim.x + threadIdx.x) >> 5;
    int lane = threadIdx.x & 31;
    if (w >= N) return;
    float4 z = ((const float4*)(g_z + (size_t)w * D))[lane];
    float4 a = ((const float4*)aSl)[lane];
    float4 b = ((const float4*)aDl)[lane];
    float s = z.x * a.x + z.y * a.y + z.z * a.z + z.w * a.w;
    float dd = z.x * b.x + z.y * b.y + z.z * b.z + z.w * b.w;
#pragma unroll
    for (int o = 16; o; o >>= 1) {
        s += __shfl_xor_sync(0xffffffffu, s, o);
        dd += __shfl_xor_sync(0xffffffffu, dd, o);
    }
    if (lane == 0) { g_el[w] = s; g_er[w] = dd; }
}

// ---------------- fused node-centric aggregation ----------------
// One warp per node (grid-strided). Online softmax over in-edges entirely in
// registers: no segment-max pass, no denom atomics, no RED on agg. Also folds
// /denom, *snorm and the BN sum/sumsq partial reduction.
template<int H>
__global__ void __launch_bounds__(256) k_nodeagg(const float* __restrict__ snorm, int N) {
    int lane = threadIdx.x & 31;
    int wid  = threadIdx.x >> 5;           // 0..7
    int gw   = blockIdx.x * 8 + wid;
    int nwarps = gridDim.x * 8;
    int hh = (H == 8) ? (lane >> 2) : 0;

    float bsum0 = 0.f, bsum1 = 0.f, bsum2 = 0.f, bsum3 = 0.f;
    float bsq0 = 0.f, bsq1 = 0.f, bsq2 = 0.f, bsq3 = 0.f;

    const float4* Z4 = (const float4*)g_z;

    for (int n = gw; n < N; n += nwarps) {
        float ern = g_er[n * H + hh];
        int j0 = g_rowptr[n], j1 = g_rowptr[n + 1];
        float m = -INFINITY, dnm = 0.f;
        float4 acc = make_float4(0.f, 0.f, 0.f, 0.f);

        int s = 0; float elv = 0.f; float4 z = make_float4(0.f, 0.f, 0.f, 0.f);
        if (j0 < j1) {
            s = __ldg(&g_srcs[j0]);
            elv = g_el[s * H + hh];
            z = Z4[(size_t)s * 32 + lane];
        }
        for (int j = j0; j < j1; j++) {
            int s2 = 0; float el2 = 0.f; float4 z2 = make_float4(0.f, 0.f, 0.f, 0.f);
            if (j + 1 < j1) {
                s2 = __ldg(&g_srcs[j + 1]);
                el2 = g_el[s2 * H + hh];
                z2 = Z4[(size_t)s2 * 32 + lane];
            }
            float e = elv + ern;
            e = e > 0.f ? e : 0.01f * e;
            float mn = fmaxf(m, e);
            float sc = __expf(m - mn);
            float w  = __expf(e - mn);
            dnm = dnm * sc + w;
            acc.x = fmaf(acc.x, sc, w * z.x);
            acc.y = fmaf(acc.y, sc, w * z.y);
            acc.z = fmaf(acc.z, sc, w * z.z);
            acc.w = fmaf(acc.w, sc, w * z.w);
            m = mn; s = s2; elv = el2; z = z2;
        }
        float inv = (dnm > 0.f) ? (snorm[n] / dnm) : 0.f;
        float4 t = make_float4(acc.x * inv, acc.y * inv, acc.z * inv, acc.w * inv);
        ((float4*)g_agg)[(size_t)n * 32 + lane] = t;
        bsum0 += t.x; bsum1 += t.y; bsum2 += t.z; bsum3 += t.w;
        bsq0 += t.x * t.x; bsq1 += t.y * t.y; bsq2 += t.z * t.z; bsq3 += t.w * t.w;
    }

    // block-level BN reduction, one global atomic per channel per block
    __shared__ float sS[128], sQ[128];
    if (threadIdx.x < 128) { sS[threadIdx.x] = 0.f; sQ[threadIdx.x] = 0.f; }
    __syncthreads();
    int c0 = lane * 4;
    atomicAdd(&sS[c0 + 0], bsum0); atomicAdd(&sQ[c0 + 0], bsq0);
    atomicAdd(&sS[c0 + 1], bsum1); atomicAdd(&sQ[c0 + 1], bsq1);
    atomicAdd(&sS[c0 + 2], bsum2); atomicAdd(&sQ[c0 + 2], bsq2);
    atomicAdd(&sS[c0 + 3], bsum3); atomicAdd(&sQ[c0 + 3], bsq3);
    __syncthreads();
    if (threadIdx.x < 128) {
        atomicAdd(&g_bnsum[threadIdx.x], sS[threadIdx.x]);
        atomicAdd(&g_bnsq[threadIdx.x], sQ[threadIdx.x]);
    }
}

// ---------------- BN apply + ELU + residual ----------------
__global__ void k_apply(const float* __restrict__ hin, float* __restrict__ hout,
                        const float* __restrict__ gam, const float* __restrict__ bet, int N) {
    int i = blockIdx.x * blockDim.x + threadIdx.x;
    if (i >= N * D) return;
    int c = i & 127;
    float invN = 1.f / (float)N;
    float mu = g_bnsum[c] * invN;
    float var = g_bnsq[c] * invN - mu * mu;
    float x = (g_agg[i] - mu) * rsqrtf(var + BN_EPS) * gam[c] + bet[c];
    float y = x > 0.f ? x : expm1f(x);
    hout[i] = hin[i] + y;
}

// ---------------- readout: run-length segment sum (graph_ids sorted) ----------------
__global__ void k_readout(const float* __restrict__ h, const int* __restrict__ gid, int N) {
    int c = threadIdx.x; // 128
    int chunk = (N + gridDim.x - 1) / gridDim.x;
    int n0 = blockIdx.x * chunk;
    int n1 = n0 + chunk; if (n1 > N) n1 = N;
    float acc = 0.f; int gcur = -1, cnt = 0;
    for (int n = n0; n < n1; n++) {
        int g = gid[n];
        if (g != gcur) {
            if (gcur >= 0) {
                atomicAdd(&g_gsum[gcur * D + c], acc);
                if (c == 0) atomicAdd(&g_gcnt[gcur], cnt);
            }
            acc = 0.f; cnt = 0; gcur = g;
        }
        acc += h[(size_t)n * D + c]; cnt++;
    }
    if (gcur >= 0) {
        atomicAdd(&g_gsum[gcur * D + c], acc);
        if (c == 0) atomicAdd(&g_gcnt[gcur], cnt);
    }
}

// ---------------- MLP readout: 128 -> 64 -> 32 -> 10 per graph ----------------
__global__ void k_mlp(const float* __restrict__ w1, const float* __restrict__ b1,
                      const float* __restrict__ w2, const float* __restrict__ b2,
                      const float* __restrict__ w3, const float* __restrict__ b3,
                      float* __restrict__ out) {
    int g = blockIdx.x, t = threadIdx.x; // 128 threads
    __shared__ float sh[128], s1[64], s2[32];
    float cnt = (float)g_gcnt[g]; if (cnt < 1.f) cnt = 1.f;
    sh[t] = g_gsum[g * D + t] / cnt;
    __syncthreads();
    if (t < 64) {
        float a = b1[t];
        for (int k = 0; k < 128; k++) a += sh[k] * w1[k * 64 + t];
        s1[t] = a > 0.f ? a : 0.f;
    }
    __syncthreads();
    if (t < 32) {
        float a = b2[t];
        for (int k = 0; k < 64; k++) a += s1[k] * w2[k * 32 + t];
        s2[t] = a > 0.f ? a : 0.f;
    }
    __syncthreads();
    if (t < 10) {
        float a = b3[t];
        for (int k = 0; k < 32; k++) a += s2[k] * w3[k * 10 + t];
        out[g * 10 + t] = a;
    }
}

// ---------------- host orchestration ----------------
static float* symf(const void* s) { void* p = nullptr; cudaGetSymbolAddress(&p, s); return (float*)p; }

extern "C" void kernel_launch(void* const* d_in, const int* in_sizes, int n_in,
                              void* d_out, int out_size) {
    const float* nodes_feat = (const float*)d_in[0];
    const float* snorm      = (const float*)d_in[1];
    const float* emb_W      = (const float*)d_in[2];
    const float* emb_b      = (const float*)d_in[3];
    const float* fcW        = (const float*)d_in[4];
    const float* aS         = (const float*)d_in[5];
    const float* aD         = (const float*)d_in[6];
    const float* gamma      = (const float*)d_in[7];
    const float* beta       = (const float*)d_in[8];
    const float* fcW_last   = (const float*)d_in[9];
    const float* aS_last    = (const float*)d_in[10];
    const float* aD_last    = (const float*)d_in[11];
    const float* g_last     = (const float*)d_in[12];
    const float* b_last     = (const float*)d_in[13];
    const float* w1 = (const float*)d_in[14]; const float* b1 = (const float*)d_in[15];
    const float* w2 = (const float*)d_in[16]; const float* b2 = (const float*)d_in[17];
    const float* w3 = (const float*)d_in[18]; const float* b3 = (const float*)d_in[19];
    const int* src = (const int*)d_in[20];
    const int* dst = (const int*)d_in[21];
    const int* gid = (const int*)d_in[22];

    int N = in_sizes[0] / D;
    int E = in_sizes[20];
    float* out = (float*)d_out;

    float* hA = symf(g_hA);
    float* hB = symf(g_hB);
    float* zp = symf(g_z);
    float* wf = symf(g_wflat);

    dim3 ggrid(2, (N + 63) / 64);
    int nd_blocks = (N * D + 255) / 256;
    int e_blocks = (E + 255) / 256;

    // Build CSR (dst fixed for the whole forward pass) — once per call
    k_zero_cnt<<<(N + 255) / 256, 256>>>(N);
    k_hist<<<e_blocks, 256>>>(dst, E);
    k_scan<<<1, 1024>>>(N, E);
    k_scatter<<<e_blocks, 256>>>(src, dst, E);

    // embedding
    k_gemm<<<ggrid, 256>>>(nodes_feat, emb_W, emb_b, hA, N);

    const float* hin = hA;
    float* hout = hB;

    // 3 multi-head layers (H=8, O=16)
    for (int l = 0; l < 3; l++) {
        k_transpose<<<(D * D + 255) / 256, 256>>>(fcW + (size_t)l * 8 * D * 16);
        k_gemm<<<ggrid, 256>>>(hin, wf, nullptr, zp, N);
        k_attn8<<<(N * 8 + 255) / 256, 256>>>(aS + l * 128, aD + l * 128, N);
        k_zero_bn<<<1, 128>>>();
        k_nodeagg<8><<<592, 256>>>(snorm, N);
        k_apply<<<nd_blocks, 256>>>(hin, hout, gamma + l * 128, beta + l * 128, N);
        const float* tmp = hin; hin = hout; hout = (float*)tmp;
    }

    // last layer (H=1, O=128)
    {
        k_gemm<<<ggrid, 256>>>(hin, fcW_last, nullptr, zp, N);
        k_attn1<<<(N * 32 + 255) / 256, 256>>>(aS_last, aD_last, N);
        k_zero_bn<<<1, 128>>>();
        k_nodeagg<1><<<592, 256>>>(snorm, N);
        k_apply<<<nd_blocks, 256>>>(hin, hout, g_last, b_last, N);
        const float* tmp = hin; hin = hout; hout = (float*)tmp;
    }

    // readout
    k_zero_readout<<<(GMAXX * D + 255) / 256, 256>>>();
    k_readout<<<512, 128>>>(hin, gid, N);
    k_mlp<<<GMAXX, 128>>>(w1, b1, w2, b2, w3, b3, out);
}

// round 5
// speedup vs baseline: 2.0207x; 1.0106x over previous
#include <cuda_runtime.h>
#include <cuda_fp16.h>
#include <math.h>

// Problem constants (fixed by setup_inputs)
#define D        128
#define GMAXX    256
#define NMAXX    50048
#define EMAXX    1600000
#define BN_EPS   1e-5f

// ---------------- scratch (device globals; no allocation allowed) ----------------
__device__ float g_hA[NMAXX * D];
__device__ float g_hB[NMAXX * D];
__device__ float g_z[NMAXX * D];
__device__ __half g_zh[NMAXX * D];
__device__ float g_agg[NMAXX * D];
__device__ float g_el[NMAXX * 8];
__device__ float g_er[NMAXX * 8];
__device__ float g_wflat[D * D];
__device__ float g_bnsum[D];
__device__ float g_bnsq[D];
__device__ float g_gsum[GMAXX * D];
__device__ int   g_gcnt[GMAXX];
// CSR scratch
__device__ int   g_cnt[NMAXX];
__device__ int   g_rowptr[NMAXX + 1];
__device__ int   g_cursor[NMAXX];
__device__ int   g_srcs[EMAXX];

// ---------------- CSR build ----------------
__global__ void k_zero_cnt(int N) {
    int i = blockIdx.x * blockDim.x + threadIdx.x;
    if (i < N) g_cnt[i] = 0;
}

__global__ void k_hist(const int* __restrict__ dst, int E) {
    int e = blockIdx.x * blockDim.x + threadIdx.x;
    if (e < E) atomicAdd(&g_cnt[dst[e]], 1);
}

// single-block exclusive scan over g_cnt -> g_rowptr/g_cursor
__global__ void k_scan(int N, int E) {
    __shared__ int warp_sums[32];
    __shared__ int s_carry;
    int t = threadIdx.x;          // 1024 threads
    int lane = t & 31, wid = t >> 5;
    if (t == 0) s_carry = 0;
    __syncthreads();
    for (int base = 0; base < N; base += 1024) {
        int i = base + t;
        int v = (i < N) ? g_cnt[i] : 0;
        int x = v;
#pragma unroll
        for (int off = 1; off < 32; off <<= 1) {
            int y = __shfl_up_sync(0xffffffffu, x, off);
            if (lane >= off) x += y;
        }
        if (lane == 31) warp_sums[wid] = x;
        __syncthreads();
        if (wid == 0) {
            int w = warp_sums[lane];
#pragma unroll
            for (int off = 1; off < 32; off <<= 1) {
                int y = __shfl_up_sync(0xffffffffu, w, off);
                if (lane >= off) w += y;
            }
            warp_sums[lane] = w;
        }
        __syncthreads();
        int incl = x + (wid > 0 ? warp_sums[wid - 1] : 0);
        int excl = incl - v + s_carry;
        if (i < N) { g_rowptr[i] = excl; g_cursor[i] = excl; }
        __syncthreads();
        if (t == 1023) s_carry += incl;
        __syncthreads();
    }
    if (t == 0) g_rowptr[N] = E;
}

__global__ void k_scatter(const int* __restrict__ src, const int* __restrict__ dst, int E) {
    int e = blockIdx.x * blockDim.x + threadIdx.x;
    if (e >= E) return;
    int d = dst[e];
    int pos = atomicAdd(&g_cursor[d], 1);
    g_srcs[pos] = src[e];
}

// ---------------- misc init ----------------
__global__ void k_zero_bn() {
    int i = threadIdx.x;
    if (i < D) { g_bnsum[i] = 0.f; g_bnsq[i] = 0.f; }
}

__global__ void k_zero_readout() {
    int i = blockIdx.x * blockDim.x + threadIdx.x;
    if (i < GMAXX * D) g_gsum[i] = 0.f;
    if (i < GMAXX) g_gcnt[i] = 0;
}

// ---------------- GEMM: C[N,128] = A[N,128] * B[128,128] ----------------
// Epilogue options: bias add, fp32 store, fp16 store, fused per-head attn logits.
// For ATTN: each 64-col block covers 4 complete heads (16 cols each); el/er
// reduce over the 4-lane tx-group via shfl — no atomics.
template<bool BIAS, bool STF32, bool STH, bool ATTN>
__global__ void k_gemm(const float* __restrict__ A, const float* __restrict__ B,
                       const float* __restrict__ bias, float* __restrict__ C,
                       const float* __restrict__ aSl, const float* __restrict__ aDl, int N)
{
    __shared__ __align__(16) float Ast[16][68]; // [k][row], padded
    __shared__ __align__(16) float Bs[16][64];  // [k][col]
    int tid = threadIdx.x;
    int tx = tid & 15, ty = tid >> 4;
    int row0 = blockIdx.y * 64;
    int col0 = blockIdx.x * 64;

    float acc[4][4];
#pragma unroll
    for (int i = 0; i < 4; i++)
#pragma unroll
        for (int j = 0; j < 4; j++) acc[i][j] = 0.f;

    for (int kt = 0; kt < 8; kt++) {
        {
            int r = tid >> 2;
            int kq = (tid & 3) * 4;
            int gr = row0 + r; if (gr >= N) gr = N - 1;
            const float4 av = *(const float4*)(A + (size_t)gr * D + kt * 16 + kq);
            Ast[kq + 0][r] = av.x; Ast[kq + 1][r] = av.y;
            Ast[kq + 2][r] = av.z; Ast[kq + 3][r] = av.w;
        }
        {
            int k = tid >> 4;
            int c4 = (tid & 15) * 4;
            *(float4*)&Bs[k][c4] = *(const float4*)(B + (size_t)(kt * 16 + k) * D + col0 + c4);
        }
        __syncthreads();
#pragma unroll
        for (int k = 0; k < 16; k++) {
            float4 a = *(float4*)&Ast[k][ty * 4];
            float4 b = *(float4*)&Bs[k][tx * 4];
            acc[0][0] += a.x * b.x; acc[0][1] += a.x * b.y; acc[0][2] += a.x * b.z; acc[0][3] += a.x * b.w;
            acc[1][0] += a.y * b.x; acc[1][1] += a.y * b.y; acc[1][2] += a.y * b.z; acc[1][3] += a.y * b.w;
            acc[2][0] += a.z * b.x; acc[2][1] += a.z * b.y; acc[2][2] += a.z * b.z; acc[2][3] += a.z * b.w;
            acc[3][0] += a.w * b.x; acc[3][1] += a.w * b.y; acc[3][2] += a.w * b.z; acc[3][3] += a.w * b.w;
        }
        __syncthreads();
    }

    int c0 = col0 + tx * 4;
    float4 bv = make_float4(0.f, 0.f, 0.f, 0.f);
    if (BIAS) bv = *(const float4*)(bias + c0);
    float4 as4 = make_float4(0.f, 0.f, 0.f, 0.f), ad4 = as4;
    if (ATTN) { as4 = *(const float4*)(aSl + c0); ad4 = *(const float4*)(aDl + c0); }
    int lane = tid & 31;

#pragma unroll
    for (int i = 0; i < 4; i++) {
        int r = row0 + ty * 4 + i;
        float4 v = make_float4(acc[i][0] + bv.x, acc[i][1] + bv.y,
                               acc[i][2] + bv.z, acc[i][3] + bv.w);
        if (ATTN) {
            float el = v.x * as4.x + v.y * as4.y + v.z * as4.z + v.w * as4.w;
            float er = v.x * ad4.x + v.y * ad4.y + v.z * ad4.z + v.w * ad4.w;
            el += __shfl_xor_sync(0xffffffffu, el, 1);
            el += __shfl_xor_sync(0xffffffffu, el, 2);
            er += __shfl_xor_sync(0xffffffffu, er, 1);
            er += __shfl_xor_sync(0xffffffffu, er, 2);
            if ((lane & 3) == 0 && r < N) {
                int h = blockIdx.x * 4 + ((lane & 15) >> 2);
                g_el[r * 8 + h] = el;
                g_er[r * 8 + h] = er;
            }
        }
        if (r < N) {
            if (STF32) *(float4*)(C + (size_t)r * D + c0) = v;
            if (STH) {
                __half2 h0 = __floats2half2_rn(v.x, v.y);
                __half2 h1 = __floats2half2_rn(v.z, v.w);
                *(__half2*)(&g_zh[(size_t)r * D + c0])     = h0;
                *(__half2*)(&g_zh[(size_t)r * D + c0 + 2]) = h1;
            }
        }
    }
}

// ---------------- weight reshape: wflat[d*128 + h*16+o] = fcW[h][d][o] ----------------
__global__ void k_transpose(const float* __restrict__ fcWl) {
    int i = blockIdx.x * blockDim.x + threadIdx.x;
    if (i >= D * D) return;
    int d = i >> 7, c = i & 127;
    int h = c >> 4, o = c & 15;
    g_wflat[i] = fcWl[(h * D + d) * 16 + o];
}

// ---------------- attention logits for last layer (H=1, full 128 dot) ----------------
__global__ void k_attn1(const float* __restrict__ aSl, const float* __restrict__ aDl, int N) {
    int w = (blockIdx.x * blockDim.x + threadIdx.x) >> 5;
    int lane = threadIdx.x & 31;
    if (w >= N) return;
    float4 z = ((const float4*)(g_z + (size_t)w * D))[lane];
    float4 a = ((const float4*)aSl)[lane];
    float4 b = ((const float4*)aDl)[lane];
    float s = z.x * a.x + z.y * a.y + z.z * a.z + z.w * a.w;
    float dd = z.x * b.x + z.y * b.y + z.z * b.z + z.w * b.w;
#pragma unroll
    for (int o = 16; o; o >>= 1) {
        s += __shfl_xor_sync(0xffffffffu, s, o);
        dd += __shfl_xor_sync(0xffffffffu, dd, o);
    }
    if (lane == 0) { g_el[w] = s; g_er[w] = dd; }
}

// ---------------- fused node-centric aggregation (fp16 z gather) ----------------
template<int H>
__global__ void __launch_bounds__(256) k_nodeagg(const float* __restrict__ snorm, int N) {
    int lane = threadIdx.x & 31;
    int wid  = threadIdx.x >> 5;           // 0..7
    int gw   = blockIdx.x * 8 + wid;
    int nwarps = gridDim.x * 8;
    int hh = (H == 8) ? (lane >> 2) : 0;

    float bsum0 = 0.f, bsum1 = 0.f, bsum2 = 0.f, bsum3 = 0.f;
    float bsq0 = 0.f, bsq1 = 0.f, bsq2 = 0.f, bsq3 = 0.f;

    const uint2* Z2 = (const uint2*)g_zh;   // 4 halfs per lane

    for (int n = gw; n < N; n += nwarps) {
        float ern = g_er[n * H + hh];
        int j0 = g_rowptr[n], j1 = g_rowptr[n + 1];
        float m = -INFINITY, dnm = 0.f;
        float4 acc = make_float4(0.f, 0.f, 0.f, 0.f);

        float elv = 0.f; uint2 zr = make_uint2(0u, 0u);
        if (j0 < j1) {
            int s = __ldg(&g_srcs[j0]);
            elv = g_el[s * H + hh];
            zr = Z2[(size_t)s * 32 + lane];
        }
        for (int j = j0; j < j1; j++) {
            float el2 = 0.f; uint2 zr2 = make_uint2(0u, 0u);
            if (j + 1 < j1) {
                int s2 = __ldg(&g_srcs[j + 1]);
                el2 = g_el[s2 * H + hh];
                zr2 = Z2[(size_t)s2 * 32 + lane];
            }
            float2 f0 = __half22float2(*(__half2*)&zr.x);
            float2 f1 = __half22float2(*(__half2*)&zr.y);
            float e = elv + ern;
            e = e > 0.f ? e : 0.01f * e;
            float mn = fmaxf(m, e);
            float sc = __expf(m - mn);
            float w  = __expf(e - mn);
            dnm = dnm * sc + w;
            acc.x = fmaf(acc.x, sc, w * f0.x);
            acc.y = fmaf(acc.y, sc, w * f0.y);
            acc.z = fmaf(acc.z, sc, w * f1.x);
            acc.w = fmaf(acc.w, sc, w * f1.y);
            m = mn; elv = el2; zr = zr2;
        }
        float inv = (dnm > 0.f) ? (snorm[n] / dnm) : 0.f;
        float4 t = make_float4(acc.x * inv, acc.y * inv, acc.z * inv, acc.w * inv);
        ((float4*)g_agg)[(size_t)n * 32 + lane] = t;
        bsum0 += t.x; bsum1 += t.y; bsum2 += t.z; bsum3 += t.w;
        bsq0 += t.x * t.x; bsq1 += t.y * t.y; bsq2 += t.z * t.z; bsq3 += t.w * t.w;
    }

    // block-level BN reduction, one global atomic per channel per block
    __shared__ float sS[128], sQ[128];
    if (threadIdx.x < 128) { sS[threadIdx.x] = 0.f; sQ[threadIdx.x] = 0.f; }
    __syncthreads();
    int c0 = lane * 4;
    atomicAdd(&sS[c0 + 0], bsum0); atomicAdd(&sQ[c0 + 0], bsq0);
    atomicAdd(&sS[c0 + 1], bsum1); atomicAdd(&sQ[c0 + 1], bsq1);
    atomicAdd(&sS[c0 + 2], bsum2); atomicAdd(&sQ[c0 + 2], bsq2);
    atomicAdd(&sS[c0 + 3], bsum3); atomicAdd(&sQ[c0 + 3], bsq3);
    __syncthreads();
    if (threadIdx.x < 128) {
        atomicAdd(&g_bnsum[threadIdx.x], sS[threadIdx.x]);
        atomicAdd(&g_bnsq[threadIdx.x], sQ[threadIdx.x]);
    }
}

// ---------------- BN apply + ELU + residual ----------------
__global__ void k_apply(const float* __restrict__ hin, float* __restrict__ hout,
                        const float* __restrict__ gam, const float* __restrict__ bet, int N) {
    int i = blockIdx.x * blockDim.x + threadIdx.x;
    if (i >= N * D) return;
    int c = i & 127;
    float invN = 1.f / (float)N;
    float mu = g_bnsum[c] * invN;
    float var = g_bnsq[c] * invN - mu * mu;
    float x = (g_agg[i] - mu) * rsqrtf(var + BN_EPS) * gam[c] + bet[c];
    float y = x > 0.f ? x : expm1f(x);
    hout[i] = hin[i] + y;
}

// ---------------- readout: run-length segment sum (graph_ids sorted) ----------------
__global__ void k_readout(const float* __restrict__ h, const int* __restrict__ gid, int N) {
    int c = threadIdx.x; // 128
    int chunk = (N + gridDim.x - 1) / gridDim.x;
    int n0 = blockIdx.x * chunk;
    int n1 = n0 + chunk; if (n1 > N) n1 = N;
    float acc = 0.f; int gcur = -1, cnt = 0;
    for (int n = n0; n < n1; n++) {
        int g = gid[n];
        if (g != gcur) {
            if (gcur >= 0) {
                atomicAdd(&g_gsum[gcur * D + c], acc);
                if (c == 0) atomicAdd(&g_gcnt[gcur], cnt);
            }
            acc = 0.f; cnt = 0; gcur = g;
        }
        acc += h[(size_t)n * D + c]; cnt++;
    }
    if (gcur >= 0) {
        atomicAdd(&g_gsum[gcur * D + c], acc);
        if (c == 0) atomicAdd(&g_gcnt[gcur], cnt);
    }
}

// ---------------- MLP readout: 128 -> 64 -> 32 -> 10 per graph ----------------
__global__ void k_mlp(const float* __restrict__ w1, const float* __restrict__ b1,
                      const float* __restrict__ w2, const float* __restrict__ b2,
                      const float* __restrict__ w3, const float* __restrict__ b3,
                      float* __restrict__ out) {
    int g = blockIdx.x, t = threadIdx.x; // 128 threads
    __shared__ float sh[128], s1[64], s2[32];
    float cnt = (float)g_gcnt[g]; if (cnt < 1.f) cnt = 1.f;
    sh[t] = g_gsum[g * D + t] / cnt;
    __syncthreads();
    if (t < 64) {
        float a = b1[t];
        for (int k = 0; k < 128; k++) a += sh[k] * w1[k * 64 + t];
        s1[t] = a > 0.f ? a : 0.f;
    }
    __syncthreads();
    if (t < 32) {
        float a = b2[t];
        for (int k = 0; k < 64; k++) a += s1[k] * w2[k * 32 + t];
        s2[t] = a > 0.f ? a : 0.f;
    }
    __syncthreads();
    if (t < 10) {
        float a = b3[t];
        for (int k = 0; k < 32; k++) a += s2[k] * w3[k * 10 + t];
        out[g * 10 + t] = a;
    }
}

// ---------------- host orchestration ----------------
static float* symf(const void* s) { void* p = nullptr; cudaGetSymbolAddress(&p, s); return (float*)p; }

extern "C" void kernel_launch(void* const* d_in, const int* in_sizes, int n_in,
                              void* d_out, int out_size) {
    const float* nodes_feat = (const float*)d_in[0];
    const float* snorm      = (const float*)d_in[1];
    const float* emb_W      = (const float*)d_in[2];
    const float* emb_b      = (const float*)d_in[3];
    const float* fcW        = (const float*)d_in[4];
    const float* aS         = (const float*)d_in[5];
    const float* aD         = (const float*)d_in[6];
    const float* gamma      = (const float*)d_in[7];
    const float* beta       = (const float*)d_in[8];
    const float* fcW_last   = (const float*)d_in[9];
    const float* aS_last    = (const float*)d_in[10];
    const float* aD_last    = (const float*)d_in[11];
    const float* g_last     = (const float*)d_in[12];
    const float* b_last     = (const float*)d_in[13];
    const float* w1 = (const float*)d_in[14]; const float* b1 = (const float*)d_in[15];
    const float* w2 = (const float*)d_in[16]; const float* b2 = (const float*)d_in[17];
    const float* w3 = (const float*)d_in[18]; const float* b3 = (const float*)d_in[19];
    const int* src = (const int*)d_in[20];
    const int* dst = (const int*)d_in[21];
    const int* gid = (const int*)d_in[22];

    int N = in_sizes[0] / D;
    int E = in_sizes[20];
    float* out = (float*)d_out;

    float* hA = symf(g_hA);
    float* hB = symf(g_hB);
    float* zp = symf(g_z);
    float* wf = symf(g_wflat);

    dim3 ggrid(2, (N + 63) / 64);
    int nd_blocks = (N * D + 255) / 256;
    int e_blocks = (E + 255) / 256;

    // Build CSR (dst fixed for the whole forward pass) — once per call
    k_zero_cnt<<<(N + 255) / 256, 256>>>(N);
    k_hist<<<e_blocks, 256>>>(dst, E);
    k_scan<<<1, 1024>>>(N, E);
    k_scatter<<<e_blocks, 256>>>(src, dst, E);

    // embedding: bias, fp32 store only
    k_gemm<true, true, false, false><<<ggrid, 256>>>(nodes_feat, emb_W, emb_b, hA,
                                                     nullptr, nullptr, N);

    const float* hin = hA;
    float* hout = hB;

    // 3 multi-head layers (H=8, O=16): half store + fused attn, no fp32 z
    for (int l = 0; l < 3; l++) {
        k_transpose<<<(D * D + 255) / 256, 256>>>(fcW + (size_t)l * 8 * D * 16);
        k_gemm<false, false, true, true><<<ggrid, 256>>>(hin, wf, nullptr, nullptr,
                                                         aS + l * 128, aD + l * 128, N);
        k_zero_bn<<<1, 128>>>();
        k_nodeagg<8><<<592, 256>>>(snorm, N);
        k_apply<<<nd_blocks, 256>>>(hin, hout, gamma + l * 128, beta + l * 128, N);
        const float* tmp = hin; hin = hout; hout = (float*)tmp;
    }

    // last layer (H=1, O=128): need fp32 z for attn1 + half for gather
    {
        k_gemm<false, true, true, false><<<ggrid, 256>>>(hin, fcW_last, nullptr, zp,
                                                         nullptr, nullptr, N);
        k_attn1<<<(N * 32 + 255) / 256, 256>>>(aS_last, aD_last, N);
        k_zero_bn<<<1, 128>>>();
        k_nodeagg<1><<<592, 256>>>(snorm, N);
        k_apply<<<nd_blocks, 256>>>(hin, hout, g_last, b_last, N);
        const float* tmp = hin; hin = hout; hout = (float*)tmp;
    }

    // readout
    k_zero_readout<<<(GMAXX * D + 255) / 256, 256>>>();
    k_readout<<<512, 128>>>(hin, gid, N);
    k_mlp<<<GMAXX, 128>>>(w1, b1, w2, b2, w3, b3, out);
}

// round 7
// speedup vs baseline: 2.3441x; 1.1600x over previous
#include <cuda_runtime.h>
#include <cuda_fp16.h>
#include <stdint.h>
#include <math.h>

// Problem constants (fixed by setup_inputs)
#define D        128
#define GMAXX    256
#define NMAXX    50048
#define EMAXX    1600000
#define BN_EPS   1e-5f

// ---------------- scratch (device globals; no allocation allowed) ----------------
__device__ float  g_hA[NMAXX * D];
__device__ float  g_hB[NMAXX * D];
__device__ __half g_hh[NMAXX * D];   // fp16 mirror of current h (GEMM A input)
__device__ __half g_zh[NMAXX * D];   // fp16 z (gather source)
__device__ float  g_agg[NMAXX * D];
__device__ float  g_el[NMAXX * 8];
__device__ float  g_er[NMAXX * 8];
__device__ uint2  g_bperm[4096];     // B fragments: [kt(8)][nt(16)][lane(32)] -> {b0,b1}
__device__ float  g_bnsum[D];
__device__ float  g_bnsq[D];
__device__ float  g_gsum[GMAXX * D];
__device__ int    g_gcnt[GMAXX];
// CSR scratch
__device__ int    g_cnt[NMAXX];
__device__ int    g_rowptr[NMAXX + 1];
__device__ int    g_cursor[NMAXX];
__device__ int    g_srcs[EMAXX];

// ---------------- CSR build ----------------
__global__ void k_zero_cnt(int N) {
    int i = blockIdx.x * blockDim.x + threadIdx.x;
    if (i < N) g_cnt[i] = 0;
}

__global__ void k_hist(const int* __restrict__ dst, int E) {
    int e = blockIdx.x * blockDim.x + threadIdx.x;
    if (e < E) atomicAdd(&g_cnt[dst[e]], 1);
}

__global__ void k_scan(int N, int E) {
    __shared__ int warp_sums[32];
    __shared__ int s_carry;
    int t = threadIdx.x;          // 1024 threads
    int lane = t & 31, wid = t >> 5;
    if (t == 0) s_carry = 0;
    __syncthreads();
    for (int base = 0; base < N; base += 1024) {
        int i = base + t;
        int v = (i < N) ? g_cnt[i] : 0;
        int x = v;
#pragma unroll
        for (int off = 1; off < 32; off <<= 1) {
            int y = __shfl_up_sync(0xffffffffu, x, off);
            if (lane >= off) x += y;
        }
        if (lane == 31) warp_sums[wid] = x;
        __syncthreads();
        if (wid == 0) {
            int w = warp_sums[lane];
#pragma unroll
            for (int off = 1; off < 32; off <<= 1) {
                int y = __shfl_up_sync(0xffffffffu, w, off);
                if (lane >= off) w += y;
            }
            warp_sums[lane] = w;
        }
        __syncthreads();
        int incl = x + (wid > 0 ? warp_sums[wid - 1] : 0);
        int excl = incl - v + s_carry;
        if (i < N) { g_rowptr[i] = excl; g_cursor[i] = excl; }
        __syncthreads();
        if (t == 1023) s_carry += incl;
        __syncthreads();
    }
    if (t == 0) g_rowptr[N] = E;
}

__global__ void k_scatter(const int* __restrict__ src, const int* __restrict__ dst, int E) {
    int e = blockIdx.x * blockDim.x + threadIdx.x;
    if (e >= E) return;
    int d = dst[e];
    int pos = atomicAdd(&g_cursor[d], 1);
    g_srcs[pos] = src[e];
}

// ---------------- misc ----------------
__global__ void k_zero_bn() {
    int i = threadIdx.x;
    if (i < D) { g_bnsum[i] = 0.f; g_bnsq[i] = 0.f; }
}

__global__ void k_zero_readout() {
    int i = blockIdx.x * blockDim.x + threadIdx.x;
    if (i < GMAXX * D) g_gsum[i] = 0.f;
    if (i < GMAXX) g_gcnt[i] = 0;
}

// fp32 -> fp16 conversion (vectorized), count = elements/4
__global__ void k_f2h(const float* __restrict__ in, __half* __restrict__ out, int n4) {
    int i = blockIdx.x * blockDim.x + threadIdx.x;
    if (i >= n4) return;
    float4 v = ((const float4*)in)[i];
    __half2 h0 = __floats2half2_rn(v.x, v.y);
    __half2 h1 = __floats2half2_rn(v.z, v.w);
    uint2 u;
    u.x = *(uint32_t*)&h0; u.y = *(uint32_t*)&h1;
    ((uint2*)out)[i] = u;
}

// ---------------- B fragment pre-permute ----------------
// mode 0: W row-major [k*128+n] (emb_W, fcW_last)
// mode 1: fcW layer [h][d][o]: W[((n>>4)*128 + k)*16 + (n&15)]
__global__ void k_prepB(const float* __restrict__ W, int mode) {
    int i = blockIdx.x * blockDim.x + threadIdx.x;
    if (i >= 4096) return;
    int lane = i & 31, nt = (i >> 5) & 15, kt = i >> 9;
    int gid = lane >> 2, tig = lane & 3;
    int n = nt * 8 + gid;
    int k0 = kt * 16 + tig * 2;
    float w0, w1, w2, w3;
    if (mode) {
        const float* base = W + ((n >> 4) * 128) * 16 + (n & 15);
        w0 = base[(k0    ) * 16]; w1 = base[(k0 + 1) * 16];
        w2 = base[(k0 + 8) * 16]; w3 = base[(k0 + 9) * 16];
    } else {
        w0 = W[(k0    ) * 128 + n]; w1 = W[(k0 + 1) * 128 + n];
        w2 = W[(k0 + 8) * 128 + n]; w3 = W[(k0 + 9) * 128 + n];
    }
    __half2 b0 = __floats2half2_rn(w0, w1);
    __half2 b1 = __floats2half2_rn(w2, w3);
    uint2 u; u.x = *(uint32_t*)&b0; u.y = *(uint32_t*)&b1;
    g_bperm[i] = u;
}

// ---------------- tensor-core GEMM: C[N,128] = A[N,128] * B[128,128] ----------------
// 256 threads = 8 warps, each warp owns 16 rows x 128 cols. No smem.
// Epilogue: optional bias, fp32 store, fp16 store, fused attn logits (H heads).
__device__ __forceinline__ void mma16816(float* c, uint32_t a0, uint32_t a1,
                                         uint32_t a2, uint32_t a3,
                                         uint32_t b0, uint32_t b1) {
    asm("mma.sync.aligned.m16n8k16.row.col.f32.f16.f16.f32 "
        "{%0,%1,%2,%3}, {%4,%5,%6,%7}, {%8,%9}, {%0,%1,%2,%3};"
        : "+f"(c[0]), "+f"(c[1]), "+f"(c[2]), "+f"(c[3])
        : "r"(a0), "r"(a1), "r"(a2), "r"(a3), "r"(b0), "r"(b1));
}

template<bool BIAS, bool STF32, bool STH, bool ATTN, int H>
__global__ void __launch_bounds__(256) k_gemm16(
    const __half* __restrict__ Ah, float* __restrict__ Cf, __half* __restrict__ Ch,
    const float* __restrict__ bias,
    const float* __restrict__ aSl, const float* __restrict__ aDl, int N)
{
    int lane = threadIdx.x & 31, wid = threadIdx.x >> 5;
    int row0 = blockIdx.x * 128 + wid * 16;
    int gid = lane >> 2, tig = lane & 3;
    int rA = row0 + gid, rB = rA + 8;
    int rAc = rA < N ? rA : N - 1;
    int rBc = rB < N ? rB : N - 1;

    float acc[16][4];
#pragma unroll
    for (int nt = 0; nt < 16; nt++)
#pragma unroll
        for (int q = 0; q < 4; q++) acc[nt][q] = 0.f;

#pragma unroll
    for (int kt = 0; kt < 8; kt++) {
        size_t kA = (size_t)rAc * D + kt * 16 + tig * 2;
        size_t kB = (size_t)rBc * D + kt * 16 + tig * 2;
        uint32_t a0 = *(const uint32_t*)(Ah + kA);
        uint32_t a1 = *(const uint32_t*)(Ah + kB);
        uint32_t a2 = *(const uint32_t*)(Ah + kA + 8);
        uint32_t a3 = *(const uint32_t*)(Ah + kB + 8);
#pragma unroll
        for (int nt = 0; nt < 16; nt++) {
            uint2 b = g_bperm[(kt * 16 + nt) * 32 + lane];
            mma16816(acc[nt], a0, a1, a2, a3, b.x, b.y);
        }
    }

    if (BIAS) {
#pragma unroll
        for (int nt = 0; nt < 16; nt++) {
            float2 bv = *(const float2*)(bias + nt * 8 + tig * 2);
            acc[nt][0] += bv.x; acc[nt][1] += bv.y;
            acc[nt][2] += bv.x; acc[nt][3] += bv.y;
        }
    }

    if (ATTN) {
#pragma unroll
        for (int h = 0; h < (H == 8 ? 8 : 1); h++) {
            float elA = 0.f, erA = 0.f, elB = 0.f, erB = 0.f;
            const int nt0 = (H == 8) ? 2 * h : 0;
            const int ntn = (H == 8) ? 2 : 16;
#pragma unroll
            for (int q = 0; q < ntn; q++) {
                int nt = nt0 + q;
                int col = nt * 8 + tig * 2;
                float2 s2 = *(const float2*)(aSl + col);
                float2 d2 = *(const float2*)(aDl + col);
                elA += acc[nt][0] * s2.x + acc[nt][1] * s2.y;
                erA += acc[nt][0] * d2.x + acc[nt][1] * d2.y;
                elB += acc[nt][2] * s2.x + acc[nt][3] * s2.y;
                erB += acc[nt][2] * d2.x + acc[nt][3] * d2.y;
            }
            elA += __shfl_xor_sync(0xffffffffu, elA, 1); elA += __shfl_xor_sync(0xffffffffu, elA, 2);
            erA += __shfl_xor_sync(0xffffffffu, erA, 1); erA += __shfl_xor_sync(0xffffffffu, erA, 2);
            elB += __shfl_xor_sync(0xffffffffu, elB, 1); elB += __shfl_xor_sync(0xffffffffu, elB, 2);
            erB += __shfl_xor_sync(0xffffffffu, erB, 1); erB += __shfl_xor_sync(0xffffffffu, erB, 2);
            if (tig == 0) {
                if (rA < N) { g_el[rA * H + h] = elA; g_er[rA * H + h] = erA; }
                if (rB < N) { g_el[rB * H + h] = elB; g_er[rB * H + h] = erB; }
            }
        }
    }

#pragma unroll
    for (int nt = 0; nt < 16; nt++) {
        int col = nt * 8 + tig * 2;
        if (rA < N) {
            if (STF32) *(float2*)(Cf + (size_t)rA * D + col) = make_float2(acc[nt][0], acc[nt][1]);
            if (STH) {
                __half2 hv = __floats2half2_rn(acc[nt][0], acc[nt][1]);
                *(__half2*)(Ch + (size_t)rA * D + col) = hv;
            }
        }
        if (rB < N) {
            if (STF32) *(float2*)(Cf + (size_t)rB * D + col) = make_float2(acc[nt][2], acc[nt][3]);
            if (STH) {
                __half2 hv = __floats2half2_rn(acc[nt][2], acc[nt][3]);
                *(__half2*)(Ch + (size_t)rB * D + col) = hv;
            }
        }
    }
}

// ---------------- fused node-centric aggregation (fp16 z gather, 8-deep pipeline) ----
template<int H>
__global__ void __launch_bounds__(256) k_nodeagg(const float* __restrict__ snorm, int N) {
    int lane = threadIdx.x & 31;
    int wid  = threadIdx.x >> 5;           // 0..7
    int gw   = blockIdx.x * 8 + wid;
    int nwarps = gridDim.x * 8;
    int hh = (H == 8) ? (lane >> 2) : 0;

    float bsum0 = 0.f, bsum1 = 0.f, bsum2 = 0.f, bsum3 = 0.f;
    float bsq0 = 0.f, bsq1 = 0.f, bsq2 = 0.f, bsq3 = 0.f;

    const uint2* Z2 = (const uint2*)g_zh;   // 4 halfs per lane

    for (int n = gw; n < N; n += nwarps) {
        float ern = g_er[n * H + hh];
        int j0 = g_rowptr[n], j1 = g_rowptr[n + 1];
        float m = -INFINITY, dnm = 0.f;
        float4 acc = make_float4(0.f, 0.f, 0.f, 0.f);

        int j = j0;
        while (j < j1) {
            int c = j1 - j; if (c > 8) c = 8;
            int ss[8]; float ee[8]; uint2 zz[8];
#pragma unroll
            for (int t = 0; t < 8; t++)
                if (t < c) ss[t] = __ldg(&g_srcs[j + t]);
#pragma unroll
            for (int t = 0; t < 8; t++)
                if (t < c) {
                    ee[t] = __ldg(&g_el[ss[t] * H + hh]);
                    zz[t] = __ldg(&Z2[(size_t)ss[t] * 32 + lane]);
                }
#pragma unroll
            for (int t = 0; t < 8; t++)
                if (t < c) {
                    float e = ee[t] + ern;
                    e = e > 0.f ? e : 0.01f * e;
                    float mn = fmaxf(m, e);
                    float sc = __expf(m - mn);
                    float w  = __expf(e - mn);
                    dnm = dnm * sc + w;
                    float2 f0 = __half22float2(*(__half2*)&zz[t].x);
                    float2 f1 = __half22float2(*(__half2*)&zz[t].y);
                    acc.x = fmaf(acc.x, sc, w * f0.x);
                    acc.y = fmaf(acc.y, sc, w * f0.y);
                    acc.z = fmaf(acc.z, sc, w * f1.x);
                    acc.w = fmaf(acc.w, sc, w * f1.y);
                    m = mn;
                }
            j += c;
        }
        float inv = (dnm > 0.f) ? (snorm[n] / dnm) : 0.f;
        float4 t = make_float4(acc.x * inv, acc.y * inv, acc.z * inv, acc.w * inv);
        ((float4*)g_agg)[(size_t)n * 32 + lane] = t;
        bsum0 += t.x; bsum1 += t.y; bsum2 += t.z; bsum3 += t.w;
        bsq0 += t.x * t.x; bsq1 += t.y * t.y; bsq2 += t.z * t.z; bsq3 += t.w * t.w;
    }

    __shared__ float sS[128], sQ[128];
    if (threadIdx.x < 128) { sS[threadIdx.x] = 0.f; sQ[threadIdx.x] = 0.f; }
    __syncthreads();
    int c0 = lane * 4;
    atomicAdd(&sS[c0 + 0], bsum0); atomicAdd(&sQ[c0 + 0], bsq0);
    atomicAdd(&sS[c0 + 1], bsum1); atomicAdd(&sQ[c0 + 1], bsq1);
    atomicAdd(&sS[c0 + 2], bsum2); atomicAdd(&sQ[c0 + 2], bsq2);
    atomicAdd(&sS[c0 + 3], bsum3); atomicAdd(&sQ[c0 + 3], bsq3);
    __syncthreads();
    if (threadIdx.x < 128) {
        atomicAdd(&g_bnsum[threadIdx.x], sS[threadIdx.x]);
        atomicAdd(&g_bnsq[threadIdx.x], sQ[threadIdx.x]);
    }
}

// ---------------- BN apply + ELU + residual (+ fp16 mirror for next GEMM) ----------
__global__ void k_apply(const float* __restrict__ hin, float* __restrict__ hout,
                        const float* __restrict__ gam, const float* __restrict__ bet, int N) {
    int i = blockIdx.x * blockDim.x + threadIdx.x;
    if (i >= N * D) return;
    int c = i & 127;
    float invN = 1.f / (float)N;
    float mu = g_bnsum[c] * invN;
    float var = g_bnsq[c] * invN - mu * mu;
    float x = (g_agg[i] - mu) * rsqrtf(var + BN_EPS) * gam[c] + bet[c];
    float y = x > 0.f ? x : expm1f(x);
    float r = hin[i] + y;
    hout[i] = r;
    g_hh[i] = __float2half(r);
}

// ---------------- readout: run-length segment sum (graph_ids sorted) ----------------
__global__ void k_readout(const float* __restrict__ h, const int* __restrict__ gid, int N) {
    int c = threadIdx.x; // 128
    int chunk = (N + gridDim.x - 1) / gridDim.x;
    int n0 = blockIdx.x * chunk;
    int n1 = n0 + chunk; if (n1 > N) n1 = N;
    float acc = 0.f; int gcur = -1, cnt = 0;
    for (int n = n0; n < n1; n++) {
        int g = gid[n];
        if (g != gcur) {
            if (gcur >= 0) {
                atomicAdd(&g_gsum[gcur * D + c], acc);
                if (c == 0) atomicAdd(&g_gcnt[gcur], cnt);
            }
            acc = 0.f; cnt = 0; gcur = g;
        }
        acc += h[(size_t)n * D + c]; cnt++;
    }
    if (gcur >= 0) {
        atomicAdd(&g_gsum[gcur * D + c], acc);
        if (c == 0) atomicAdd(&g_gcnt[gcur], cnt);
    }
}

// ---------------- MLP readout: 128 -> 64 -> 32 -> 10 per graph ----------------
__global__ void k_mlp(const float* __restrict__ w1, const float* __restrict__ b1,
                      const float* __restrict__ w2, const float* __restrict__ b2,
                      const float* __restrict__ w3, const float* __restrict__ b3,
                      float* __restrict__ out) {
    int g = blockIdx.x, t = threadIdx.x; // 128 threads
    __shared__ float sh[128], s1[64], s2[32];
    float cnt = (float)g_gcnt[g]; if (cnt < 1.f) cnt = 1.f;
    sh[t] = g_gsum[g * D + t] / cnt;
    __syncthreads();
    if (t < 64) {
        float a = b1[t];
        for (int k = 0; k < 128; k++) a += sh[k] * w1[k * 64 + t];
        s1[t] = a > 0.f ? a : 0.f;
    }
    __syncthreads();
    if (t < 32) {
        float a = b2[t];
        for (int k = 0; k < 64; k++) a += s1[k] * w2[k * 32 + t];
        s2[t] = a > 0.f ? a : 0.f;
    }
    __syncthreads();
    if (t < 10) {
        float a = b3[t];
        for (int k = 0; k < 32; k++) a += s2[k] * w3[k * 10 + t];
        out[g * 10 + t] = a;
    }
}

// ---------------- host orchestration ----------------
static float* symf(const void* s) { void* p = nullptr; cudaGetSymbolAddress(&p, s); return (float*)p; }
static __half* symh(const void* s) { void* p = nullptr; cudaGetSymbolAddress(&p, s); return (__half*)p; }

extern "C" void kernel_launch(void* const* d_in, const int* in_sizes, int n_in,
                              void* d_out, int out_size) {
    const float* nodes_feat = (const float*)d_in[0];
    const float* snorm      = (const float*)d_in[1];
    const float* emb_W      = (const float*)d_in[2];
    const float* emb_b      = (const float*)d_in[3];
    const float* fcW        = (const float*)d_in[4];
    const float* aS         = (const float*)d_in[5];
    const float* aD         = (const float*)d_in[6];
    const float* gamma      = (const float*)d_in[7];
    const float* beta       = (const float*)d_in[8];
    const float* fcW_last   = (const float*)d_in[9];
    const float* aS_last    = (const float*)d_in[10];
    const float* aD_last    = (const float*)d_in[11];
    const float* g_last     = (const float*)d_in[12];
    const float* b_last     = (const float*)d_in[13];
    const float* w1 = (const float*)d_in[14]; const float* b1 = (const float*)d_in[15];
    const float* w2 = (const float*)d_in[16]; const float* b2 = (const float*)d_in[17];
    const float* w3 = (const float*)d_in[18]; const float* b3 = (const float*)d_in[19];
    const int* src = (const int*)d_in[20];
    const int* dst = (const int*)d_in[21];
    const int* gid = (const int*)d_in[22];

    int N = in_sizes[0] / D;
    int E = in_sizes[20];
    float* out = (float*)d_out;

    float*  hA = symf(g_hA);
    float*  hB = symf(g_hB);
    __half* hh = symh(g_hh);
    __half* zh = symh(g_zh);

    int gblocks = (N + 127) / 128;
    int nd_blocks = (N * D + 255) / 256;
    int e_blocks = (E + 255) / 256;
    int f2h_blocks = (N * D / 4 + 255) / 256;

    // Build CSR (dst fixed for the whole forward pass)
    k_zero_cnt<<<(N + 255) / 256, 256>>>(N);
    k_hist<<<e_blocks, 256>>>(dst, E);
    k_scan<<<1, 1024>>>(N, E);
    k_scatter<<<e_blocks, 256>>>(src, dst, E);

    // embedding: A = fp16(nodes_feat), out = fp32 hA
    k_f2h<<<f2h_blocks, 256>>>(nodes_feat, hh, N * D / 4);
    k_prepB<<<16, 256>>>(emb_W, 0);
    k_gemm16<true, true, false, false, 8><<<gblocks, 256>>>(hh, hA, zh, emb_b,
                                                            nullptr, nullptr, N);
    k_f2h<<<f2h_blocks, 256>>>(hA, hh, N * D / 4);

    const float* hin = hA;
    float* hout = hB;

    // 3 multi-head layers (H=8, O=16)
    for (int l = 0; l < 3; l++) {
        k_prepB<<<16, 256>>>(fcW + (size_t)l * 8 * D * 16, 1);
        k_gemm16<false, false, true, true, 8><<<gblocks, 256>>>(hh, nullptr, zh, nullptr,
                                                                aS + l * 128, aD + l * 128, N);
        k_zero_bn<<<1, 128>>>();
        k_nodeagg<8><<<592, 256>>>(snorm, N);
        k_apply<<<nd_blocks, 256>>>(hin, hout, gamma + l * 128, beta + l * 128, N);
        const float* tmp = hin; hin = hout; hout = (float*)tmp;
    }

    // last layer (H=1, O=128): fused 128-wide attn logits, fp16 z only
    {
        k_prepB<<<16, 256>>>(fcW_last, 0);
        k_gemm16<false, false, true, true, 1><<<gblocks, 256>>>(hh, nullptr, zh, nullptr,
                                                                aS_last, aD_last, N);
        k_zero_bn<<<1, 128>>>();
        k_nodeagg<1><<<592, 256>>>(snorm, N);
        k_apply<<<nd_blocks, 256>>>(hin, hout, g_last, b_last, N);
        const float* tmp = hin; hin = hout; hout = (float*)tmp;
    }

    // readout
    k_zero_readout<<<(GMAXX * D + 255) / 256, 256>>>();
    k_readout<<<512, 128>>>(hin, gid, N);
    k_mlp<<<GMAXX, 128>>>(w1, b1, w2, b2, w3, b3, out);
}